// round 5
// baseline (speedup 1.0000x reference)
#include <cuda_runtime.h>
#include <cuda_bf16.h>
#include <cstdint>
#include <math.h>

namespace {
constexpr int kB   = 4;
constexpr int kLq  = 512;
constexpr int kLkv = 2048;
constexpr int kDim = 1024;
constexpr int kH   = 16;
constexpr int kMlp = 4096;
constexpr int kNQ  = kB * kLq;    // 2048
constexpr int kNKV = kB * kLkv;   // 8192
}

__device__ __align__(256) unsigned char g_scratch[160u * 1024u * 1024u];

#define CP_ASYNC16(dst, src) \
    asm volatile("cp.async.cg.shared.global [%0], [%1], 16;" :: "r"(dst), "l"(src))
#define CP_COMMIT() asm volatile("cp.async.commit_group;")
#define LDSM4(r0,r1,r2,r3,addr) \
    asm volatile("ldmatrix.sync.aligned.m8n8.x4.shared.b16 {%0,%1,%2,%3}, [%4];" \
        : "=r"(r0),"=r"(r1),"=r"(r2),"=r"(r3) : "r"(addr))
#define LDSM4T(r0,r1,r2,r3,addr) \
    asm volatile("ldmatrix.sync.aligned.m8n8.x4.trans.shared.b16 {%0,%1,%2,%3}, [%4];" \
        : "=r"(r0),"=r"(r1),"=r"(r2),"=r"(r3) : "r"(addr))
#define MMA16816(d,a0,a1,a2,a3,b0,b1) \
    asm volatile("mma.sync.aligned.m16n8k16.row.col.f32.bf16.bf16.f32 " \
        "{%0,%1,%2,%3}, {%4,%5,%6,%7}, {%8,%9}, {%0,%1,%2,%3};" \
        : "+f"(d[0]),"+f"(d[1]),"+f"(d[2]),"+f"(d[3]) \
        : "r"(a0),"r"(a1),"r"(a2),"r"(a3),"r"(b0),"r"(b1))

__device__ __forceinline__ uint32_t pack_bf16(float a, float b) {
    __nv_bfloat162 t = __floats2bfloat162_rn(a, b);
    return *reinterpret_cast<uint32_t*>(&t);
}

// ---------------------------------------------------------------------------
// Merged f32 -> bf16 weight convert
// dst layout (elements): Wq@0, Wk@1M, Wv@2M, Wo@3M, fc1@4M, fc2@8M
// ---------------------------------------------------------------------------
__global__ __launch_bounds__(256) void cvt_all_kernel(
    const float* __restrict__ Wq, const float* __restrict__ Wk,
    const float* __restrict__ Wv, const float* __restrict__ Wo,
    const float* __restrict__ fc1, const float* __restrict__ fc2,
    __nv_bfloat16* __restrict__ dst)
{
    const size_t M1 = 1u << 20;
    size_t gid = (size_t)blockIdx.x * 1024 + threadIdx.x * 4;
    const float* src; size_t off;
    if (gid < 4 * M1) {
        int si = (int)(gid >> 20);
        src = (si == 0) ? Wq : (si == 1) ? Wk : (si == 2) ? Wv : Wo;
        off = gid & (M1 - 1);
    } else if (gid < 8 * M1) { src = fc1; off = gid - 4 * M1; }
    else                     { src = fc2; off = gid - 8 * M1; }
    float4 v = *reinterpret_cast<const float4*>(src + off);
    *reinterpret_cast<__nv_bfloat162*>(dst + gid)     = __floats2bfloat162_rn(v.x, v.y);
    *reinterpret_cast<__nv_bfloat162*>(dst + gid + 2) = __floats2bfloat162_rn(v.z, v.w);
}

// ---------------------------------------------------------------------------
// LayerNorm (fp32 -> bf16)
// ---------------------------------------------------------------------------
__global__ __launch_bounds__(256) void ln_bf16_kernel(
    const float* __restrict__ x, const float* __restrict__ w,
    const float* __restrict__ b, __nv_bfloat16* __restrict__ y)
{
    int row = blockIdx.x;
    const float* xr = x + (size_t)row * kDim;
    __nv_bfloat16* yr = y + (size_t)row * kDim;
    int t = threadIdx.x;

    float4 xv = reinterpret_cast<const float4*>(xr)[t];
    float s  = xv.x + xv.y + xv.z + xv.w;
    float s2 = xv.x*xv.x + xv.y*xv.y + xv.z*xv.z + xv.w*xv.w;

    #pragma unroll
    for (int off = 16; off > 0; off >>= 1) {
        s  += __shfl_xor_sync(0xffffffffu, s,  off);
        s2 += __shfl_xor_sync(0xffffffffu, s2, off);
    }
    __shared__ float rs[8], rs2[8];
    int wid = t >> 5;
    if ((t & 31) == 0) { rs[wid] = s; rs2[wid] = s2; }
    __syncthreads();
    s = 0.f; s2 = 0.f;
    #pragma unroll
    for (int i = 0; i < 8; i++) { s += rs[i]; s2 += rs2[i]; }

    float mu  = s * (1.0f / kDim);
    float var = s2 * (1.0f / kDim) - mu * mu;
    float r   = rsqrtf(var + 1e-6f);

    float4 wv = reinterpret_cast<const float4*>(w)[t];
    float4 bv = reinterpret_cast<const float4*>(b)[t];
    reinterpret_cast<__nv_bfloat162*>(yr)[2*t] =
        __floats2bfloat162_rn((xv.x - mu) * r * wv.x + bv.x,
                              (xv.y - mu) * r * wv.y + bv.y);
    reinterpret_cast<__nv_bfloat162*>(yr)[2*t+1] =
        __floats2bfloat162_rn((xv.z - mu) * r * wv.z + bv.z,
                              (xv.w - mu) * r * wv.w + bv.w);
}

// ---------------------------------------------------------------------------
// bf16 mma.sync GEMM: C[M,N] = A[M,K] @ W[N,K]^T (fp32 accum)
// BM=128, BN in {128, 64}, BK=64, 256 threads (8 warps, 4x2 layout,
// warp tile 32 x BN/2), 3-stage cp.async pipeline.
// EPI 1: bf16 GELU(acc+bias).  EPI 2: fp32 res + alpha*(acc+bias).
// EPI 3: bf16 per-head (64-col) L2-norm (BN=128 only).  EPI 4: bf16 plain.
// ---------------------------------------------------------------------------
template <int EPI, int BN>
__global__ __launch_bounds__(256) void gemm_bf16_kernel(
    const __nv_bfloat16* __restrict__ A, const __nv_bfloat16* __restrict__ W,
    int M, int N, int K,
    const float* __restrict__ bias, const float* __restrict__ res,
    const float* __restrict__ alpha,
    float* __restrict__ Cf, __nv_bfloat16* __restrict__ Cb)
{
    constexpr int NFR  = BN / 16;               // 8-wide n-frags per warp
    constexpr int NB16 = BN / 32;               // 16-row B ldsm groups per warp
    constexpr uint32_t kStageBytes = 16384u + (uint32_t)BN * 128u;
    constexpr int kStages = 3;
    constexpr int LTOT = (128 + BN) * 8;        // 16B-chunk tasks per stage
    constexpr int LITER = LTOT / 256;

    extern __shared__ char smem_raw[];
    const uint32_t smem = (uint32_t)__cvta_generic_to_shared(smem_raw);

    const int tid  = threadIdx.x;
    const int lane = tid & 31;
    const int w    = tid >> 5;
    const int wm   = (w & 3) << 5;
    const int wn   = (w >> 2) * (BN / 2);
    const long m0  = (long)blockIdx.y << 7;
    const long n0  = (long)blockIdx.x * BN;

    const __nv_bfloat16* Ag = A + m0 * K;
    const __nv_bfloat16* Wg = W + n0 * K;

    auto load_tile = [&](int t, int s) {
        uint32_t sA = smem + (uint32_t)s * kStageBytes;
        uint32_t sB = sA + 16384;
        const __nv_bfloat16* a = Ag + (long)t * 64;
        const __nv_bfloat16* b = Wg + (long)t * 64;
        #pragma unroll
        for (int p = 0; p < LITER; p++) {
            int idx = tid + p * 256;
            int row = idx >> 3, ch = idx & 7;
            if (row < 128) {
                uint32_t doff = row * 128 + ((uint32_t)(ch ^ (row & 7)) << 4);
                CP_ASYNC16(sA + doff, a + (long)row * K + ch * 8);
            } else {
                int r = row - 128;
                uint32_t doff = r * 128 + ((uint32_t)(ch ^ (r & 7)) << 4);
                CP_ASYNC16(sB + doff, b + (long)r * K + ch * 8);
            }
        }
    };

    float acc[2][NFR][4];
    #pragma unroll
    for (int i = 0; i < 2; i++)
        #pragma unroll
        for (int j = 0; j < NFR; j++)
            #pragma unroll
            for (int c = 0; c < 4; c++) acc[i][j][c] = 0.f;

    const int T = K >> 6;

    load_tile(0, 0); CP_COMMIT();
    load_tile(1, 1); CP_COMMIT();

    for (int kt = 0; kt < T; kt++) {
        int s = kt % kStages;
        asm volatile("cp.async.wait_group 1;" ::: "memory");
        __syncthreads();

        // prefetch tile kt+2 into the free stage (overlaps compute below)
        if (kt + 2 < T) {
            load_tile(kt + 2, (kt + 2) % kStages);
            CP_COMMIT();
        } else {
            CP_COMMIT();  // keep group accounting uniform
        }

        uint32_t sA = smem + (uint32_t)s * kStageBytes;
        uint32_t sB = sA + 16384;
        #pragma unroll
        for (int ks = 0; ks < 4; ks++) {
            uint32_t afr[2][4];
            #pragma unroll
            for (int im = 0; im < 2; im++) {
                int row = wm + im * 16 + (lane & 15);
                int ch  = ks * 2 + (lane >> 4);
                uint32_t addr = sA + row * 128 + ((uint32_t)(ch ^ (row & 7)) << 4);
                LDSM4(afr[im][0], afr[im][1], afr[im][2], afr[im][3], addr);
            }
            uint32_t bfr[NFR][2];
            #pragma unroll
            for (int ib = 0; ib < NB16; ib++) {
                int row = wn + ib * 16 + ((lane >> 4) << 3) + (lane & 7);
                int ch  = ks * 2 + ((lane >> 3) & 1);
                uint32_t addr = sB + row * 128 + ((uint32_t)(ch ^ (row & 7)) << 4);
                uint32_t r0, r1, r2, r3;
                LDSM4(r0, r1, r2, r3, addr);
                bfr[2*ib][0] = r0; bfr[2*ib][1] = r1;
                bfr[2*ib+1][0] = r2; bfr[2*ib+1][1] = r3;
            }
            #pragma unroll
            for (int im = 0; im < 2; im++)
                #pragma unroll
                for (int in = 0; in < NFR; in++)
                    MMA16816(acc[im][in], afr[im][0], afr[im][1], afr[im][2], afr[im][3],
                             bfr[in][0], bfr[in][1]);
        }
        __syncthreads();
    }

    const int g = lane >> 2, tg = lane & 3;
    float al = (EPI == 2) ? alpha[0] : 0.f;
    #pragma unroll
    for (int im = 0; im < 2; im++) {
        long r0 = m0 + wm + im * 16 + g;
        float inv0 = 1.f, inv1 = 1.f;
        if (EPI == 3) {
            float ss0 = 0.f, ss1 = 0.f;
            #pragma unroll
            for (int in = 0; in < NFR; in++) {
                ss0 += acc[im][in][0]*acc[im][in][0] + acc[im][in][1]*acc[im][in][1];
                ss1 += acc[im][in][2]*acc[im][in][2] + acc[im][in][3]*acc[im][in][3];
            }
            ss0 += __shfl_xor_sync(0xffffffffu, ss0, 1);
            ss0 += __shfl_xor_sync(0xffffffffu, ss0, 2);
            ss1 += __shfl_xor_sync(0xffffffffu, ss1, 1);
            ss1 += __shfl_xor_sync(0xffffffffu, ss1, 2);
            inv0 = 1.0f / fmaxf(sqrtf(ss0), 1e-6f);
            inv1 = 1.0f / fmaxf(sqrtf(ss1), 1e-6f);
        }
        #pragma unroll
        for (int in = 0; in < NFR; in++) {
            long c = n0 + wn + in * 8 + tg * 2;
            float v0 = acc[im][in][0], v1 = acc[im][in][1];
            float v2 = acc[im][in][2], v3 = acc[im][in][3];
            if (EPI == 1) {
                float b0 = bias[c], b1 = bias[c + 1];
                v0 += b0; v1 += b1; v2 += b0; v3 += b1;
                const float is2 = 0.7071067811865475f;
                v0 = 0.5f * v0 * (1.f + erff(v0 * is2));
                v1 = 0.5f * v1 * (1.f + erff(v1 * is2));
                v2 = 0.5f * v2 * (1.f + erff(v2 * is2));
                v3 = 0.5f * v3 * (1.f + erff(v3 * is2));
                *reinterpret_cast<__nv_bfloat162*>(&Cb[r0 * N + c]) =
                    __floats2bfloat162_rn(v0, v1);
                *reinterpret_cast<__nv_bfloat162*>(&Cb[(r0 + 8) * N + c]) =
                    __floats2bfloat162_rn(v2, v3);
            } else if (EPI == 2) {
                float b0 = bias[c], b1 = bias[c + 1];
                float2 ra = *reinterpret_cast<const float2*>(&res[r0 * N + c]);
                float2 rb = *reinterpret_cast<const float2*>(&res[(r0 + 8) * N + c]);
                *reinterpret_cast<float2*>(&Cf[r0 * N + c]) =
                    make_float2(ra.x + al * (v0 + b0), ra.y + al * (v1 + b1));
                *reinterpret_cast<float2*>(&Cf[(r0 + 8) * N + c]) =
                    make_float2(rb.x + al * (v2 + b0), rb.y + al * (v3 + b1));
            } else if (EPI == 3) {
                *reinterpret_cast<__nv_bfloat162*>(&Cb[r0 * N + c]) =
                    __floats2bfloat162_rn(v0 * inv0, v1 * inv0);
                *reinterpret_cast<__nv_bfloat162*>(&Cb[(r0 + 8) * N + c]) =
                    __floats2bfloat162_rn(v2 * inv1, v3 * inv1);
            } else {
                *reinterpret_cast<__nv_bfloat162*>(&Cb[r0 * N + c]) =
                    __floats2bfloat162_rn(v0, v1);
                *reinterpret_cast<__nv_bfloat162*>(&Cb[(r0 + 8) * N + c]) =
                    __floats2bfloat162_rn(v2, v3);
            }
        }
    }
}

// ---------------------------------------------------------------------------
// Tensor-core flash attention (unchanged). Grid (B*H, Lq/64), 128 threads.
// ---------------------------------------------------------------------------
__global__ __launch_bounds__(128) void attn_mma_kernel(
    const __nv_bfloat16* __restrict__ q, const __nv_bfloat16* __restrict__ k,
    const __nv_bfloat16* __restrict__ v, __nv_bfloat16* __restrict__ ctx)
{
    __shared__ __align__(1024) unsigned char sm[40 * 1024];
    const uint32_t smem = (uint32_t)__cvta_generic_to_shared(sm);
    const uint32_t sQ = smem;

    const int bh = blockIdx.x;
    const int b = bh >> 4, h = bh & 15;
    const int q0 = blockIdx.y * 64;
    const int tid = threadIdx.x;
    const int lane = tid & 31;
    const int w = tid >> 5;

    const __nv_bfloat16* qg = q + ((size_t)(b * kLq + q0)) * kDim + h * 64;
    const __nv_bfloat16* kg = k + ((size_t)b * kLkv) * kDim + h * 64;
    const __nv_bfloat16* vg = v + ((size_t)b * kLkv) * kDim + h * 64;

    #pragma unroll
    for (int p = 0; p < 4; p++) {
        int idx = tid + p * 128;
        int row = idx >> 3, ch = idx & 7;
        uint32_t doff = row * 128 + ((uint32_t)(ch ^ (row & 7)) << 4);
        CP_ASYNC16(sQ + doff, qg + (size_t)row * kDim + ch * 8);
        CP_ASYNC16(sQ + 8192 + doff, kg + (size_t)row * kDim + ch * 8);
        CP_ASYNC16(sQ + 16384 + doff, vg + (size_t)row * kDim + ch * 8);
    }
    CP_COMMIT();

    uint32_t qa[4][4];
    float oacc[8][4];
    #pragma unroll
    for (int j = 0; j < 8; j++)
        #pragma unroll
        for (int c = 0; c < 4; c++) oacc[j][c] = 0.f;
    float mrow[2] = {-1e30f, -1e30f};
    float lrow[2] = {0.f, 0.f};

    const int T = kLkv / 64;
    for (int t = 0; t < T; t++) {
        int s = t & 1;
        if (t + 1 < T) {
            uint32_t sK = sQ + 8192 + (s ^ 1) * 16384;
            uint32_t sV = sK + 8192;
            const __nv_bfloat16* kp = kg + (size_t)(t + 1) * 64 * kDim;
            const __nv_bfloat16* vp = vg + (size_t)(t + 1) * 64 * kDim;
            #pragma unroll
            for (int p = 0; p < 4; p++) {
                int idx = tid + p * 128;
                int row = idx >> 3, ch = idx & 7;
                uint32_t doff = row * 128 + ((uint32_t)(ch ^ (row & 7)) << 4);
                CP_ASYNC16(sK + doff, kp + (size_t)row * kDim + ch * 8);
                CP_ASYNC16(sV + doff, vp + (size_t)row * kDim + ch * 8);
            }
            CP_COMMIT();
            asm volatile("cp.async.wait_group 1;");
        } else {
            asm volatile("cp.async.wait_group 0;");
        }
        __syncthreads();

        if (t == 0) {
            #pragma unroll
            for (int ks = 0; ks < 4; ks++) {
                int row = w * 16 + (lane & 15);
                int ch  = ks * 2 + (lane >> 4);
                uint32_t addr = sQ + row * 128 + ((uint32_t)(ch ^ (row & 7)) << 4);
                LDSM4(qa[ks][0], qa[ks][1], qa[ks][2], qa[ks][3], addr);
            }
        }

        uint32_t sK = sQ + 8192 + s * 16384;
        uint32_t sV = sK + 8192;

        float sacc[8][4];
        #pragma unroll
        for (int j = 0; j < 8; j++)
            #pragma unroll
            for (int c = 0; c < 4; c++) sacc[j][c] = 0.f;

        #pragma unroll
        for (int ks = 0; ks < 4; ks++) {
            uint32_t bfr[8][2];
            #pragma unroll
            for (int ib = 0; ib < 4; ib++) {
                int row = ib * 16 + ((lane >> 4) << 3) + (lane & 7);
                int ch  = ks * 2 + ((lane >> 3) & 1);
                uint32_t addr = sK + row * 128 + ((uint32_t)(ch ^ (row & 7)) << 4);
                uint32_t r0, r1, r2, r3;
                LDSM4(r0, r1, r2, r3, addr);
                bfr[2*ib][0] = r0; bfr[2*ib][1] = r1;
                bfr[2*ib+1][0] = r2; bfr[2*ib+1][1] = r3;
            }
            #pragma unroll
            for (int j = 0; j < 8; j++)
                MMA16816(sacc[j], qa[ks][0], qa[ks][1], qa[ks][2], qa[ks][3],
                         bfr[j][0], bfr[j][1]);
        }

        float m0 = -1e30f, m1 = -1e30f;
        #pragma unroll
        for (int j = 0; j < 8; j++) {
            sacc[j][0] *= 0.5f; sacc[j][1] *= 0.5f;
            sacc[j][2] *= 0.5f; sacc[j][3] *= 0.5f;
            m0 = fmaxf(m0, fmaxf(sacc[j][0], sacc[j][1]));
            m1 = fmaxf(m1, fmaxf(sacc[j][2], sacc[j][3]));
        }
        m0 = fmaxf(m0, __shfl_xor_sync(0xffffffffu, m0, 1));
        m0 = fmaxf(m0, __shfl_xor_sync(0xffffffffu, m0, 2));
        m1 = fmaxf(m1, __shfl_xor_sync(0xffffffffu, m1, 1));
        m1 = fmaxf(m1, __shfl_xor_sync(0xffffffffu, m1, 2));
        float nm0 = fmaxf(mrow[0], m0), nm1 = fmaxf(mrow[1], m1);
        float sc0 = __expf(mrow[0] - nm0), sc1 = __expf(mrow[1] - nm1);
        mrow[0] = nm0; mrow[1] = nm1;

        float ps0 = 0.f, ps1 = 0.f;
        #pragma unroll
        for (int j = 0; j < 8; j++) {
            sacc[j][0] = __expf(sacc[j][0] - nm0);
            sacc[j][1] = __expf(sacc[j][1] - nm0);
            sacc[j][2] = __expf(sacc[j][2] - nm1);
            sacc[j][3] = __expf(sacc[j][3] - nm1);
            ps0 += sacc[j][0] + sacc[j][1];
            ps1 += sacc[j][2] + sacc[j][3];
        }
        lrow[0] = lrow[0] * sc0 + ps0;
        lrow[1] = lrow[1] * sc1 + ps1;
        #pragma unroll
        for (int j = 0; j < 8; j++) {
            oacc[j][0] *= sc0; oacc[j][1] *= sc0;
            oacc[j][2] *= sc1; oacc[j][3] *= sc1;
        }

        uint32_t pa[4][4];
        #pragma unroll
        for (int kc = 0; kc < 4; kc++) {
            pa[kc][0] = pack_bf16(sacc[2*kc][0],   sacc[2*kc][1]);
            pa[kc][1] = pack_bf16(sacc[2*kc][2],   sacc[2*kc][3]);
            pa[kc][2] = pack_bf16(sacc[2*kc+1][0], sacc[2*kc+1][1]);
            pa[kc][3] = pack_bf16(sacc[2*kc+1][2], sacc[2*kc+1][3]);
        }

        const int mi = lane >> 3;
        #pragma unroll
        for (int kc = 0; kc < 4; kc++) {
            #pragma unroll
            for (int ng = 0; ng < 4; ng++) {
                int row = kc * 16 + ((mi & 1) << 3) + (lane & 7);
                int ch  = ng * 2 + (mi >> 1);
                uint32_t addr = sV + row * 128 + ((uint32_t)(ch ^ (row & 7)) << 4);
                uint32_t r0, r1, r2, r3;
                LDSM4T(r0, r1, r2, r3, addr);
                MMA16816(oacc[2*ng],   pa[kc][0], pa[kc][1], pa[kc][2], pa[kc][3], r0, r1);
                MMA16816(oacc[2*ng+1], pa[kc][0], pa[kc][1], pa[kc][2], pa[kc][3], r2, r3);
            }
        }
        __syncthreads();
    }

    lrow[0] += __shfl_xor_sync(0xffffffffu, lrow[0], 1);
    lrow[0] += __shfl_xor_sync(0xffffffffu, lrow[0], 2);
    lrow[1] += __shfl_xor_sync(0xffffffffu, lrow[1], 1);
    lrow[1] += __shfl_xor_sync(0xffffffffu, lrow[1], 2);
    float inv0 = 1.0f / lrow[0], inv1 = 1.0f / lrow[1];

    const int g = lane >> 2, tg = lane & 3;
    size_t r0 = (size_t)(b * kLq + q0 + w * 16 + g) * kDim + h * 64;
    #pragma unroll
    for (int j = 0; j < 8; j++) {
        int c = j * 8 + tg * 2;
        *reinterpret_cast<__nv_bfloat162*>(&ctx[r0 + c]) =
            __floats2bfloat162_rn(oacc[j][0] * inv0, oacc[j][1] * inv0);
        *reinterpret_cast<__nv_bfloat162*>(&ctx[r0 + 8 * kDim + c]) =
            __floats2bfloat162_rn(oacc[j][2] * inv1, oacc[j][3] * inv1);
    }
}

// ---------------------------------------------------------------------------
// kernel_launch
// ---------------------------------------------------------------------------
extern "C" void kernel_launch(void* const* d_in, const int* in_sizes, int n_in,
                              void* d_out, int out_size)
{
    const float* q_tokens   = (const float*)d_in[0];
    const float* kv_tokens  = (const float*)d_in[1];
    const float* q_ln_w     = (const float*)d_in[2];
    const float* q_ln_b     = (const float*)d_in[3];
    const float* kv_ln_w    = (const float*)d_in[4];
    const float* kv_ln_b    = (const float*)d_in[5];
    const float* mlp_ln_w   = (const float*)d_in[6];
    const float* mlp_ln_b   = (const float*)d_in[7];
    const float* Wq         = (const float*)d_in[8];
    const float* Wk         = (const float*)d_in[9];
    const float* Wv         = (const float*)d_in[10];
    const float* Wo         = (const float*)d_in[11];
    const float* bo         = (const float*)d_in[12];
    const float* fc1_w      = (const float*)d_in[13];
    const float* fc1_b      = (const float*)d_in[14];
    const float* fc2_w      = (const float*)d_in[15];
    const float* fc2_b      = (const float*)d_in[16];
    const float* alpha_attn = (const float*)d_in[17];
    const float* alpha_mlp  = (const float*)d_in[18];
    float* out = (float*)d_out;

    unsigned char* arena = nullptr;
    cudaGetSymbolAddress((void**)&arena, g_scratch);
    const size_t MB = 1024u * 1024u;

    __nv_bfloat16* qn   = (__nv_bfloat16*)(arena + 0 * MB);
    __nv_bfloat16* kvn  = (__nv_bfloat16*)(arena + 4 * MB);
    __nv_bfloat16* wtb  = (__nv_bfloat16*)(arena + 20 * MB);
    __nv_bfloat16* Wqb  = wtb + 0u * (1u << 20);
    __nv_bfloat16* Wkb  = wtb + 1u * (1u << 20);
    __nv_bfloat16* Wvb  = wtb + 2u * (1u << 20);
    __nv_bfloat16* Wob  = wtb + 3u * (1u << 20);
    __nv_bfloat16* fc1b = wtb + 4u * (1u << 20);
    __nv_bfloat16* fc2b = wtb + 8u * (1u << 20);
    __nv_bfloat16* qb   = (__nv_bfloat16*)(arena + 44 * MB);
    __nv_bfloat16* kb   = (__nv_bfloat16*)(arena + 48 * MB);
    __nv_bfloat16* vb   = (__nv_bfloat16*)(arena + 64 * MB);
    __nv_bfloat16* ctxb = (__nv_bfloat16*)(arena + 80 * MB);
    __nv_bfloat16* hln  = (__nv_bfloat16*)(arena + 84 * MB);
    __nv_bfloat16* h1b  = (__nv_bfloat16*)(arena + 88 * MB);

    constexpr uint32_t kSmem128 = 3u * (16384u + 128u * 128u);  // 98304
    constexpr uint32_t kSmem64  = 3u * (16384u + 64u * 128u);   // 73728

    cudaFuncSetAttribute(gemm_bf16_kernel<1,128>, cudaFuncAttributeMaxDynamicSharedMemorySize, kSmem128);
    cudaFuncSetAttribute(gemm_bf16_kernel<2,64>,  cudaFuncAttributeMaxDynamicSharedMemorySize, kSmem64);
    cudaFuncSetAttribute(gemm_bf16_kernel<3,128>, cudaFuncAttributeMaxDynamicSharedMemorySize, kSmem128);
    cudaFuncSetAttribute(gemm_bf16_kernel<4,128>, cudaFuncAttributeMaxDynamicSharedMemorySize, kSmem128);

    cvt_all_kernel<<<12288, 256>>>(Wq, Wk, Wv, Wo, fc1_w, fc2_w, wtb);

    ln_bf16_kernel<<<kNQ, 256>>>(q_tokens, q_ln_w, q_ln_b, qn);
    ln_bf16_kernel<<<kNKV, 256>>>(kv_tokens, kv_ln_w, kv_ln_b, kvn);

    // projections: Q,K fused per-head l2norm; V plain (bf16 out)
    gemm_bf16_kernel<3,128><<<dim3(kDim / 128, kNQ / 128), 256, kSmem128>>>(
        qn, Wqb, kNQ, kDim, kDim, nullptr, nullptr, nullptr, nullptr, qb);
    gemm_bf16_kernel<3,128><<<dim3(kDim / 128, kNKV / 128), 256, kSmem128>>>(
        kvn, Wkb, kNKV, kDim, kDim, nullptr, nullptr, nullptr, nullptr, kb);
    gemm_bf16_kernel<4,128><<<dim3(kDim / 128, kNKV / 128), 256, kSmem128>>>(
        kvn, Wvb, kNKV, kDim, kDim, nullptr, nullptr, nullptr, nullptr, vb);

    attn_mma_kernel<<<dim3(kB * kH, kLq / 64), 128>>>(qb, kb, vb, ctxb);

    // out = q_tokens + alpha_attn * (ctx @ Wo^T + bo)   [BN=64: 256 CTAs]
    gemm_bf16_kernel<2,64><<<dim3(kDim / 64, kNQ / 128), 256, kSmem64>>>(
        ctxb, Wob, kNQ, kDim, kDim, bo, q_tokens, alpha_attn, out, nullptr);

    ln_bf16_kernel<<<kNQ, 256>>>(out, mlp_ln_w, mlp_ln_b, hln);

    gemm_bf16_kernel<1,128><<<dim3(kMlp / 128, kNQ / 128), 256, kSmem128>>>(
        hln, fc1b, kNQ, kMlp, kDim, fc1_b, nullptr, nullptr, nullptr, h1b);

    // out = out + alpha_mlp * (h1 @ fc2^T + b2)   [BN=64: 256 CTAs]
    gemm_bf16_kernel<2,64><<<dim3(kDim / 64, kNQ / 128), 256, kSmem64>>>(
        h1b, fc2b, kNQ, kDim, kMlp, fc2_b, out, alpha_mlp, out, nullptr);
}

// round 9
// speedup vs baseline: 1.1387x; 1.1387x over previous
#include <cuda_runtime.h>
#include <cuda_bf16.h>
#include <cstdint>
#include <math.h>

namespace {
constexpr int kB   = 4;
constexpr int kLq  = 512;
constexpr int kLkv = 2048;
constexpr int kDim = 1024;
constexpr int kH   = 16;
constexpr int kMlp = 4096;
constexpr int kNQ  = kB * kLq;    // 2048
constexpr int kNKV = kB * kLkv;   // 8192
}

__device__ __align__(256) unsigned char g_scratch[160u * 1024u * 1024u];

#define CP_ASYNC16(dst, src) \
    asm volatile("cp.async.cg.shared.global [%0], [%1], 16;" :: "r"(dst), "l"(src))
#define CP_COMMIT() asm volatile("cp.async.commit_group;")
#define LDSM4(r0,r1,r2,r3,addr) \
    asm volatile("ldmatrix.sync.aligned.m8n8.x4.shared.b16 {%0,%1,%2,%3}, [%4];" \
        : "=r"(r0),"=r"(r1),"=r"(r2),"=r"(r3) : "r"(addr))
#define LDSM4T(r0,r1,r2,r3,addr) \
    asm volatile("ldmatrix.sync.aligned.m8n8.x4.trans.shared.b16 {%0,%1,%2,%3}, [%4];" \
        : "=r"(r0),"=r"(r1),"=r"(r2),"=r"(r3) : "r"(addr))
#define MMA16816(d,a0,a1,a2,a3,b0,b1) \
    asm volatile("mma.sync.aligned.m16n8k16.row.col.f32.bf16.bf16.f32 " \
        "{%0,%1,%2,%3}, {%4,%5,%6,%7}, {%8,%9}, {%0,%1,%2,%3};" \
        : "+f"(d[0]),"+f"(d[1]),"+f"(d[2]),"+f"(d[3]) \
        : "r"(a0),"r"(a1),"r"(a2),"r"(a3),"r"(b0),"r"(b1))

__device__ __forceinline__ uint32_t pack_bf16(float a, float b) {
    __nv_bfloat162 t = __floats2bfloat162_rn(a, b);
    return *reinterpret_cast<uint32_t*>(&t);
}

// ---------------------------------------------------------------------------
// Merged f32 -> bf16 weight convert
// ---------------------------------------------------------------------------
__global__ __launch_bounds__(256) void cvt_all_kernel(
    const float* __restrict__ Wq, const float* __restrict__ Wk,
    const float* __restrict__ Wv, const float* __restrict__ Wo,
    const float* __restrict__ fc1, const float* __restrict__ fc2,
    __nv_bfloat16* __restrict__ dst)
{
    const size_t M1 = 1u << 20;
    size_t gid = (size_t)blockIdx.x * 1024 + threadIdx.x * 4;
    const float* src; size_t off;
    if (gid < 4 * M1) {
        int si = (int)(gid >> 20);
        src = (si == 0) ? Wq : (si == 1) ? Wk : (si == 2) ? Wv : Wo;
        off = gid & (M1 - 1);
    } else if (gid < 8 * M1) { src = fc1; off = gid - 4 * M1; }
    else                     { src = fc2; off = gid - 8 * M1; }
    float4 v = *reinterpret_cast<const float4*>(src + off);
    *reinterpret_cast<__nv_bfloat162*>(dst + gid)     = __floats2bfloat162_rn(v.x, v.y);
    *reinterpret_cast<__nv_bfloat162*>(dst + gid + 2) = __floats2bfloat162_rn(v.z, v.w);
}

// ---------------------------------------------------------------------------
// LayerNorm core (fp32 -> bf16), one block per row
// ---------------------------------------------------------------------------
__device__ __forceinline__ void ln_row(
    const float* __restrict__ xr, const float* __restrict__ wv4,
    const float* __restrict__ bv4, __nv_bfloat16* __restrict__ yr)
{
    int t = threadIdx.x;
    float4 xv = reinterpret_cast<const float4*>(xr)[t];
    float s  = xv.x + xv.y + xv.z + xv.w;
    float s2 = xv.x*xv.x + xv.y*xv.y + xv.z*xv.z + xv.w*xv.w;

    #pragma unroll
    for (int off = 16; off > 0; off >>= 1) {
        s  += __shfl_xor_sync(0xffffffffu, s,  off);
        s2 += __shfl_xor_sync(0xffffffffu, s2, off);
    }
    __shared__ float rs[8], rs2[8];
    int wid = t >> 5;
    if ((t & 31) == 0) { rs[wid] = s; rs2[wid] = s2; }
    __syncthreads();
    s = 0.f; s2 = 0.f;
    #pragma unroll
    for (int i = 0; i < 8; i++) { s += rs[i]; s2 += rs2[i]; }

    float mu  = s * (1.0f / kDim);
    float var = s2 * (1.0f / kDim) - mu * mu;
    float r   = rsqrtf(var + 1e-6f);

    float4 wv = reinterpret_cast<const float4*>(wv4)[t];
    float4 bv = reinterpret_cast<const float4*>(bv4)[t];
    reinterpret_cast<__nv_bfloat162*>(yr)[2*t] =
        __floats2bfloat162_rn((xv.x - mu) * r * wv.x + bv.x,
                              (xv.y - mu) * r * wv.y + bv.y);
    reinterpret_cast<__nv_bfloat162*>(yr)[2*t+1] =
        __floats2bfloat162_rn((xv.z - mu) * r * wv.z + bv.z,
                              (xv.w - mu) * r * wv.w + bv.w);
}

__global__ __launch_bounds__(256) void ln_bf16_kernel(
    const float* __restrict__ x, const float* __restrict__ w,
    const float* __restrict__ b, __nv_bfloat16* __restrict__ y)
{
    int row = blockIdx.x;
    ln_row(x + (size_t)row * kDim, w, b, y + (size_t)row * kDim);
}

// merged q + kv LayerNorm (grid = kNQ + kNKV)
__global__ __launch_bounds__(256) void ln_qkv_kernel(
    const float* __restrict__ qx, const float* __restrict__ kvx,
    const float* __restrict__ qw, const float* __restrict__ qb_,
    const float* __restrict__ kvw, const float* __restrict__ kvb,
    __nv_bfloat16* __restrict__ qy, __nv_bfloat16* __restrict__ kvy)
{
    int row = blockIdx.x;
    if (row < kNQ) {
        ln_row(qx + (size_t)row * kDim, qw, qb_, qy + (size_t)row * kDim);
    } else {
        int r = row - kNQ;
        ln_row(kvx + (size_t)r * kDim, kvw, kvb, kvy + (size_t)r * kDim);
    }
}

// ---------------------------------------------------------------------------
// GEMM core: C[.,N] = A @ W^T, 128 threads, 4 warps (2x2), warp tile 64 x BN/2,
// BK=64, 3-stage cp.async pipeline, one barrier per k-iter.
// EPI 1: bf16 GELU(acc+bias).  EPI 2: fp32 res + alpha*(acc+bias).
// EPI 3: bf16, per-64-col L2-norm if do_norm else plain.
// ---------------------------------------------------------------------------
template <int EPI, int BN>
__device__ __forceinline__ void gemm_core(
    const __nv_bfloat16* __restrict__ A, const __nv_bfloat16* __restrict__ W,
    int N, int K, long m0, long n0,
    const float* __restrict__ bias, const float* __restrict__ res,
    const float* __restrict__ alpha,
    float* __restrict__ Cf, __nv_bfloat16* __restrict__ Cb,
    bool do_norm, uint32_t smem)
{
    constexpr int NW   = BN / 2;          // warp n-width
    constexpr int NFR  = NW / 8;          // n8 frags per warp
    constexpr int NB16 = NW / 16;         // 16-row B ldsm groups
    constexpr uint32_t kStageBytes = 16384u + (uint32_t)BN * 128u;
    constexpr int LITER = (128 + BN) / 16;  // cp.async per thread per tile

    const int tid  = threadIdx.x;
    const int lane = tid & 31;
    const int w    = tid >> 5;
    const int wr   = (w >> 1) * 64;
    const int wc   = (w & 1) * NW;

    const __nv_bfloat16* Ag = A + m0 * K;
    const __nv_bfloat16* Wg = W + n0 * K;

    auto load_tile = [&](int t, int s) {
        uint32_t sA = smem + (uint32_t)s * kStageBytes;
        uint32_t sB = sA + 16384;
        const __nv_bfloat16* a = Ag + (long)t * 64;
        const __nv_bfloat16* b = Wg + (long)t * 64;
        #pragma unroll
        for (int p = 0; p < LITER; p++) {
            int idx = tid + p * 128;
            int row = idx >> 3, ch = idx & 7;
            if (row < 128) {
                uint32_t doff = row * 128 + ((uint32_t)(ch ^ (row & 7)) << 4);
                CP_ASYNC16(sA + doff, a + (long)row * K + ch * 8);
            } else {
                int r = row - 128;
                uint32_t doff = r * 128 + ((uint32_t)(ch ^ (r & 7)) << 4);
                CP_ASYNC16(sB + doff, b + (long)r * K + ch * 8);
            }
        }
    };

    float acc[4][NFR][4];
    #pragma unroll
    for (int i = 0; i < 4; i++)
        #pragma unroll
        for (int j = 0; j < NFR; j++)
            #pragma unroll
            for (int c = 0; c < 4; c++) acc[i][j][c] = 0.f;

    const int T = K >> 6;

    load_tile(0, 0); CP_COMMIT();
    load_tile(1, 1); CP_COMMIT();

    for (int kt = 0; kt < T; kt++) {
        int s = kt % 3;
        asm volatile("cp.async.wait_group 1;" ::: "memory");
        __syncthreads();   // all warps done with iter kt-1; tile kt visible

        if (kt + 2 < T) load_tile(kt + 2, (kt + 2) % 3);
        CP_COMMIT();

        uint32_t sA = smem + (uint32_t)s * kStageBytes;
        uint32_t sB = sA + 16384;
        #pragma unroll
        for (int ks = 0; ks < 4; ks++) {
            uint32_t afr[4][4];
            #pragma unroll
            for (int im = 0; im < 4; im++) {
                int row = wr + im * 16 + (lane & 15);
                int ch  = ks * 2 + (lane >> 4);
                uint32_t addr = sA + row * 128 + ((uint32_t)(ch ^ (row & 7)) << 4);
                LDSM4(afr[im][0], afr[im][1], afr[im][2], afr[im][3], addr);
            }
            uint32_t bfr[NFR][2];
            #pragma unroll
            for (int ib = 0; ib < NB16; ib++) {
                int row = wc + ib * 16 + ((lane >> 4) << 3) + (lane & 7);
                int ch  = ks * 2 + ((lane >> 3) & 1);
                uint32_t addr = sB + row * 128 + ((uint32_t)(ch ^ (row & 7)) << 4);
                uint32_t r0, r1, r2, r3;
                LDSM4(r0, r1, r2, r3, addr);
                bfr[2*ib][0] = r0; bfr[2*ib][1] = r1;
                bfr[2*ib+1][0] = r2; bfr[2*ib+1][1] = r3;
            }
            #pragma unroll
            for (int im = 0; im < 4; im++)
                #pragma unroll
                for (int in = 0; in < NFR; in++)
                    MMA16816(acc[im][in], afr[im][0], afr[im][1], afr[im][2], afr[im][3],
                             bfr[in][0], bfr[in][1]);
        }
    }

    const int g = lane >> 2, tg = lane & 3;
    const float al = (EPI == 2) ? alpha[0] : 0.f;
    #pragma unroll
    for (int im = 0; im < 4; im++) {
        long r0 = m0 + wr + im * 16 + g;
        float inv0 = 1.f, inv1 = 1.f;
        if (EPI == 3) {
            if (do_norm) {
                float ss0 = 0.f, ss1 = 0.f;
                #pragma unroll
                for (int in = 0; in < NFR; in++) {
                    ss0 += acc[im][in][0]*acc[im][in][0] + acc[im][in][1]*acc[im][in][1];
                    ss1 += acc[im][in][2]*acc[im][in][2] + acc[im][in][3]*acc[im][in][3];
                }
                ss0 += __shfl_xor_sync(0xffffffffu, ss0, 1);
                ss0 += __shfl_xor_sync(0xffffffffu, ss0, 2);
                ss1 += __shfl_xor_sync(0xffffffffu, ss1, 1);
                ss1 += __shfl_xor_sync(0xffffffffu, ss1, 2);
                inv0 = 1.0f / fmaxf(sqrtf(ss0), 1e-6f);
                inv1 = 1.0f / fmaxf(sqrtf(ss1), 1e-6f);
            }
        }
        #pragma unroll
        for (int in = 0; in < NFR; in++) {
            long c = n0 + wc + in * 8 + tg * 2;
            float v0 = acc[im][in][0], v1 = acc[im][in][1];
            float v2 = acc[im][in][2], v3 = acc[im][in][3];
            if (EPI == 1) {
                float b0 = bias[c], b1 = bias[c + 1];
                v0 += b0; v1 += b1; v2 += b0; v3 += b1;
                const float is2 = 0.7071067811865475f;
                v0 = 0.5f * v0 * (1.f + erff(v0 * is2));
                v1 = 0.5f * v1 * (1.f + erff(v1 * is2));
                v2 = 0.5f * v2 * (1.f + erff(v2 * is2));
                v3 = 0.5f * v3 * (1.f + erff(v3 * is2));
                *reinterpret_cast<__nv_bfloat162*>(&Cb[r0 * N + c]) =
                    __floats2bfloat162_rn(v0, v1);
                *reinterpret_cast<__nv_bfloat162*>(&Cb[(r0 + 8) * N + c]) =
                    __floats2bfloat162_rn(v2, v3);
            } else if (EPI == 2) {
                float b0 = bias[c], b1 = bias[c + 1];
                float2 ra = *reinterpret_cast<const float2*>(&res[r0 * N + c]);
                float2 rb = *reinterpret_cast<const float2*>(&res[(r0 + 8) * N + c]);
                *reinterpret_cast<float2*>(&Cf[r0 * N + c]) =
                    make_float2(ra.x + al * (v0 + b0), ra.y + al * (v1 + b1));
                *reinterpret_cast<float2*>(&Cf[(r0 + 8) * N + c]) =
                    make_float2(rb.x + al * (v2 + b0), rb.y + al * (v3 + b1));
            } else {  // EPI 3
                *reinterpret_cast<__nv_bfloat162*>(&Cb[r0 * N + c]) =
                    __floats2bfloat162_rn(v0 * inv0, v1 * inv0);
                *reinterpret_cast<__nv_bfloat162*>(&Cb[(r0 + 8) * N + c]) =
                    __floats2bfloat162_rn(v2 * inv1, v3 * inv1);
            }
        }
    }
}

template <int EPI, int BN>
__global__ __launch_bounds__(128) void gemm_bf16_kernel(
    const __nv_bfloat16* __restrict__ A, const __nv_bfloat16* __restrict__ W,
    int N, int K,
    const float* __restrict__ bias, const float* __restrict__ res,
    const float* __restrict__ alpha,
    float* __restrict__ Cf, __nv_bfloat16* __restrict__ Cb)
{
    extern __shared__ __align__(1024) char smraw[];
    uint32_t smem = (uint32_t)__cvta_generic_to_shared(smraw);
    long m0 = (long)blockIdx.y << 7;
    long n0 = (long)blockIdx.x * BN;
    gemm_core<EPI, BN>(A, W, N, K, m0, n0, bias, res, alpha, Cf, Cb, false, smem);
}

// merged Q/K/V projection: grid.x = 128 (Q) + 512 (K) + 512 (V)
__global__ __launch_bounds__(128) void qkv_gemm_kernel(
    const __nv_bfloat16* __restrict__ qn, const __nv_bfloat16* __restrict__ kvn,
    const __nv_bfloat16* __restrict__ Wqb, const __nv_bfloat16* __restrict__ Wkb,
    const __nv_bfloat16* __restrict__ Wvb,
    __nv_bfloat16* __restrict__ qb, __nv_bfloat16* __restrict__ kb,
    __nv_bfloat16* __restrict__ vb)
{
    extern __shared__ __align__(1024) char smraw[];
    uint32_t smem = (uint32_t)__cvta_generic_to_shared(smraw);

    int bid = blockIdx.x;
    const __nv_bfloat16 *A, *W;
    __nv_bfloat16* C;
    int rel; bool do_norm;
    if (bid < 128)      { A = qn;  W = Wqb; C = qb; rel = bid;       do_norm = true;  }
    else if (bid < 640) { A = kvn; W = Wkb; C = kb; rel = bid - 128; do_norm = true;  }
    else                { A = kvn; W = Wvb; C = vb; rel = bid - 640; do_norm = false; }
    long n0 = (long)(rel & 7) << 7;
    long m0 = (long)(rel >> 3) << 7;
    gemm_core<3, 128>(A, W, kDim, kDim, m0, n0, nullptr, nullptr, nullptr,
                      nullptr, C, do_norm, smem);
}

// ---------------------------------------------------------------------------
// Tensor-core flash attention (unchanged). Grid (B*H, Lq/64), 128 threads.
// ---------------------------------------------------------------------------
__global__ __launch_bounds__(128) void attn_mma_kernel(
    const __nv_bfloat16* __restrict__ q, const __nv_bfloat16* __restrict__ k,
    const __nv_bfloat16* __restrict__ v, __nv_bfloat16* __restrict__ ctx)
{
    __shared__ __align__(1024) unsigned char sm[40 * 1024];
    const uint32_t smem = (uint32_t)__cvta_generic_to_shared(sm);
    const uint32_t sQ = smem;

    const int bh = blockIdx.x;
    const int b = bh >> 4, h = bh & 15;
    const int q0 = blockIdx.y * 64;
    const int tid = threadIdx.x;
    const int lane = tid & 31;
    const int w = tid >> 5;

    const __nv_bfloat16* qg = q + ((size_t)(b * kLq + q0)) * kDim + h * 64;
    const __nv_bfloat16* kg = k + ((size_t)b * kLkv) * kDim + h * 64;
    const __nv_bfloat16* vg = v + ((size_t)b * kLkv) * kDim + h * 64;

    #pragma unroll
    for (int p = 0; p < 4; p++) {
        int idx = tid + p * 128;
        int row = idx >> 3, ch = idx & 7;
        uint32_t doff = row * 128 + ((uint32_t)(ch ^ (row & 7)) << 4);
        CP_ASYNC16(sQ + doff, qg + (size_t)row * kDim + ch * 8);
        CP_ASYNC16(sQ + 8192 + doff, kg + (size_t)row * kDim + ch * 8);
        CP_ASYNC16(sQ + 16384 + doff, vg + (size_t)row * kDim + ch * 8);
    }
    CP_COMMIT();

    uint32_t qa[4][4];
    float oacc[8][4];
    #pragma unroll
    for (int j = 0; j < 8; j++)
        #pragma unroll
        for (int c = 0; c < 4; c++) oacc[j][c] = 0.f;
    float mrow[2] = {-1e30f, -1e30f};
    float lrow[2] = {0.f, 0.f};

    const int T = kLkv / 64;
    for (int t = 0; t < T; t++) {
        int s = t & 1;
        if (t + 1 < T) {
            uint32_t sK = sQ + 8192 + (s ^ 1) * 16384;
            uint32_t sV = sK + 8192;
            const __nv_bfloat16* kp = kg + (size_t)(t + 1) * 64 * kDim;
            const __nv_bfloat16* vp = vg + (size_t)(t + 1) * 64 * kDim;
            #pragma unroll
            for (int p = 0; p < 4; p++) {
                int idx = tid + p * 128;
                int row = idx >> 3, ch = idx & 7;
                uint32_t doff = row * 128 + ((uint32_t)(ch ^ (row & 7)) << 4);
                CP_ASYNC16(sK + doff, kp + (size_t)row * kDim + ch * 8);
                CP_ASYNC16(sV + doff, vp + (size_t)row * kDim + ch * 8);
            }
            CP_COMMIT();
            asm volatile("cp.async.wait_group 1;");
        } else {
            asm volatile("cp.async.wait_group 0;");
        }
        __syncthreads();

        if (t == 0) {
            #pragma unroll
            for (int ks = 0; ks < 4; ks++) {
                int row = w * 16 + (lane & 15);
                int ch  = ks * 2 + (lane >> 4);
                uint32_t addr = sQ + row * 128 + ((uint32_t)(ch ^ (row & 7)) << 4);
                LDSM4(qa[ks][0], qa[ks][1], qa[ks][2], qa[ks][3], addr);
            }
        }

        uint32_t sK = sQ + 8192 + s * 16384;
        uint32_t sV = sK + 8192;

        float sacc[8][4];
        #pragma unroll
        for (int j = 0; j < 8; j++)
            #pragma unroll
            for (int c = 0; c < 4; c++) sacc[j][c] = 0.f;

        #pragma unroll
        for (int ks = 0; ks < 4; ks++) {
            uint32_t bfr[8][2];
            #pragma unroll
            for (int ib = 0; ib < 4; ib++) {
                int row = ib * 16 + ((lane >> 4) << 3) + (lane & 7);
                int ch  = ks * 2 + ((lane >> 3) & 1);
                uint32_t addr = sK + row * 128 + ((uint32_t)(ch ^ (row & 7)) << 4);
                uint32_t r0, r1, r2, r3;
                LDSM4(r0, r1, r2, r3, addr);
                bfr[2*ib][0] = r0; bfr[2*ib][1] = r1;
                bfr[2*ib+1][0] = r2; bfr[2*ib+1][1] = r3;
            }
            #pragma unroll
            for (int j = 0; j < 8; j++)
                MMA16816(sacc[j], qa[ks][0], qa[ks][1], qa[ks][2], qa[ks][3],
                         bfr[j][0], bfr[j][1]);
        }

        float m0 = -1e30f, m1 = -1e30f;
        #pragma unroll
        for (int j = 0; j < 8; j++) {
            sacc[j][0] *= 0.5f; sacc[j][1] *= 0.5f;
            sacc[j][2] *= 0.5f; sacc[j][3] *= 0.5f;
            m0 = fmaxf(m0, fmaxf(sacc[j][0], sacc[j][1]));
            m1 = fmaxf(m1, fmaxf(sacc[j][2], sacc[j][3]));
        }
        m0 = fmaxf(m0, __shfl_xor_sync(0xffffffffu, m0, 1));
        m0 = fmaxf(m0, __shfl_xor_sync(0xffffffffu, m0, 2));
        m1 = fmaxf(m1, __shfl_xor_sync(0xffffffffu, m1, 1));
        m1 = fmaxf(m1, __shfl_xor_sync(0xffffffffu, m1, 2));
        float nm0 = fmaxf(mrow[0], m0), nm1 = fmaxf(mrow[1], m1);
        float sc0 = __expf(mrow[0] - nm0), sc1 = __expf(mrow[1] - nm1);
        mrow[0] = nm0; mrow[1] = nm1;

        float ps0 = 0.f, ps1 = 0.f;
        #pragma unroll
        for (int j = 0; j < 8; j++) {
            sacc[j][0] = __expf(sacc[j][0] - nm0);
            sacc[j][1] = __expf(sacc[j][1] - nm0);
            sacc[j][2] = __expf(sacc[j][2] - nm1);
            sacc[j][3] = __expf(sacc[j][3] - nm1);
            ps0 += sacc[j][0] + sacc[j][1];
            ps1 += sacc[j][2] + sacc[j][3];
        }
        lrow[0] = lrow[0] * sc0 + ps0;
        lrow[1] = lrow[1] * sc1 + ps1;
        #pragma unroll
        for (int j = 0; j < 8; j++) {
            oacc[j][0] *= sc0; oacc[j][1] *= sc0;
            oacc[j][2] *= sc1; oacc[j][3] *= sc1;
        }

        uint32_t pa[4][4];
        #pragma unroll
        for (int kc = 0; kc < 4; kc++) {
            pa[kc][0] = pack_bf16(sacc[2*kc][0],   sacc[2*kc][1]);
            pa[kc][1] = pack_bf16(sacc[2*kc][2],   sacc[2*kc][3]);
            pa[kc][2] = pack_bf16(sacc[2*kc+1][0], sacc[2*kc+1][1]);
            pa[kc][3] = pack_bf16(sacc[2*kc+1][2], sacc[2*kc+1][3]);
        }

        const int mi = lane >> 3;
        #pragma unroll
        for (int kc = 0; kc < 4; kc++) {
            #pragma unroll
            for (int ng = 0; ng < 4; ng++) {
                int row = kc * 16 + ((mi & 1) << 3) + (lane & 7);
                int ch  = ng * 2 + (mi >> 1);
                uint32_t addr = sV + row * 128 + ((uint32_t)(ch ^ (row & 7)) << 4);
                uint32_t r0, r1, r2, r3;
                LDSM4T(r0, r1, r2, r3, addr);
                MMA16816(oacc[2*ng],   pa[kc][0], pa[kc][1], pa[kc][2], pa[kc][3], r0, r1);
                MMA16816(oacc[2*ng+1], pa[kc][0], pa[kc][1], pa[kc][2], pa[kc][3], r2, r3);
            }
        }
        __syncthreads();
    }

    lrow[0] += __shfl_xor_sync(0xffffffffu, lrow[0], 1);
    lrow[0] += __shfl_xor_sync(0xffffffffu, lrow[0], 2);
    lrow[1] += __shfl_xor_sync(0xffffffffu, lrow[1], 1);
    lrow[1] += __shfl_xor_sync(0xffffffffu, lrow[1], 2);
    float inv0 = 1.0f / lrow[0], inv1 = 1.0f / lrow[1];

    const int g = lane >> 2, tg = lane & 3;
    size_t r0 = (size_t)(b * kLq + q0 + w * 16 + g) * kDim + h * 64;
    #pragma unroll
    for (int j = 0; j < 8; j++) {
        int c = j * 8 + tg * 2;
        *reinterpret_cast<__nv_bfloat162*>(&ctx[r0 + c]) =
            __floats2bfloat162_rn(oacc[j][0] * inv0, oacc[j][1] * inv0);
        *reinterpret_cast<__nv_bfloat162*>(&ctx[r0 + 8 * kDim + c]) =
            __floats2bfloat162_rn(oacc[j][2] * inv1, oacc[j][3] * inv1);
    }
}

// ---------------------------------------------------------------------------
// kernel_launch
// ---------------------------------------------------------------------------
extern "C" void kernel_launch(void* const* d_in, const int* in_sizes, int n_in,
                              void* d_out, int out_size)
{
    const float* q_tokens   = (const float*)d_in[0];
    const float* kv_tokens  = (const float*)d_in[1];
    const float* q_ln_w     = (const float*)d_in[2];
    const float* q_ln_b     = (const float*)d_in[3];
    const float* kv_ln_w    = (const float*)d_in[4];
    const float* kv_ln_b    = (const float*)d_in[5];
    const float* mlp_ln_w   = (const float*)d_in[6];
    const float* mlp_ln_b   = (const float*)d_in[7];
    const float* Wq         = (const float*)d_in[8];
    const float* Wk         = (const float*)d_in[9];
    const float* Wv         = (const float*)d_in[10];
    const float* Wo         = (const float*)d_in[11];
    const float* bo         = (const float*)d_in[12];
    const float* fc1_w      = (const float*)d_in[13];
    const float* fc1_b      = (const float*)d_in[14];
    const float* fc2_w      = (const float*)d_in[15];
    const float* fc2_b      = (const float*)d_in[16];
    const float* alpha_attn = (const float*)d_in[17];
    const float* alpha_mlp  = (const float*)d_in[18];
    float* out = (float*)d_out;

    unsigned char* arena = nullptr;
    cudaGetSymbolAddress((void**)&arena, g_scratch);
    const size_t MB = 1024u * 1024u;

    __nv_bfloat16* qn   = (__nv_bfloat16*)(arena + 0 * MB);
    __nv_bfloat16* kvn  = (__nv_bfloat16*)(arena + 4 * MB);
    __nv_bfloat16* wtb  = (__nv_bfloat16*)(arena + 20 * MB);
    __nv_bfloat16* Wqb  = wtb + 0u * (1u << 20);
    __nv_bfloat16* Wkb  = wtb + 1u * (1u << 20);
    __nv_bfloat16* Wvb  = wtb + 2u * (1u << 20);
    __nv_bfloat16* Wob  = wtb + 3u * (1u << 20);
    __nv_bfloat16* fc1b = wtb + 4u * (1u << 20);
    __nv_bfloat16* fc2b = wtb + 8u * (1u << 20);
    __nv_bfloat16* qb   = (__nv_bfloat16*)(arena + 44 * MB);
    __nv_bfloat16* kb   = (__nv_bfloat16*)(arena + 48 * MB);
    __nv_bfloat16* vb   = (__nv_bfloat16*)(arena + 64 * MB);
    __nv_bfloat16* ctxb = (__nv_bfloat16*)(arena + 80 * MB);
    __nv_bfloat16* hln  = (__nv_bfloat16*)(arena + 84 * MB);
    __nv_bfloat16* h1b  = (__nv_bfloat16*)(arena + 88 * MB);

    constexpr uint32_t kSmem128 = 3u * (16384u + 128u * 128u);  // 98304
    constexpr uint32_t kSmem64  = 3u * (16384u + 64u * 128u);   // 73728

    cudaFuncSetAttribute(qkv_gemm_kernel,         cudaFuncAttributeMaxDynamicSharedMemorySize, kSmem128);
    cudaFuncSetAttribute(gemm_bf16_kernel<1,128>, cudaFuncAttributeMaxDynamicSharedMemorySize, kSmem128);
    cudaFuncSetAttribute(gemm_bf16_kernel<2,64>,  cudaFuncAttributeMaxDynamicSharedMemorySize, kSmem64);

    cvt_all_kernel<<<12288, 256>>>(Wq, Wk, Wv, Wo, fc1_w, fc2_w, wtb);

    ln_qkv_kernel<<<kNQ + kNKV, 256>>>(q_tokens, kv_tokens, q_ln_w, q_ln_b,
                                       kv_ln_w, kv_ln_b, qn, kvn);

    // merged Q/K/V projections (Q,K fused per-head l2norm; V plain)
    qkv_gemm_kernel<<<1152, 128, kSmem128>>>(qn, kvn, Wqb, Wkb, Wvb, qb, kb, vb);

    attn_mma_kernel<<<dim3(kB * kH, kLq / 64), 128>>>(qb, kb, vb, ctxb);

    // out = q_tokens + alpha_attn * (ctx @ Wo^T + bo)
    gemm_bf16_kernel<2,64><<<dim3(kDim / 64, kNQ / 128), 128, kSmem64>>>(
        ctxb, Wob, kDim, kDim, bo, q_tokens, alpha_attn, out, nullptr);

    ln_bf16_kernel<<<kNQ, 256>>>(out, mlp_ln_w, mlp_ln_b, hln);

    gemm_bf16_kernel<1,128><<<dim3(kMlp / 128, kNQ / 128), 128, kSmem128>>>(
        hln, fc1b, kMlp, kDim, fc1_b, nullptr, nullptr, nullptr, h1b);

    // out = out + alpha_mlp * (h1 @ fc2^T + b2)
    gemm_bf16_kernel<2,64><<<dim3(kDim / 64, kNQ / 128), 128, kSmem64>>>(
        h1b, fc2b, kDim, kMlp, fc2_b, out, alpha_mlp, out, nullptr);
}